// round 15
// baseline (speedup 1.0000x reference)
#include <cuda_runtime.h>

// Problem constants (fixed by the dataset).
#define NN 50000
#define BB 64
#define EE 1600000

// Scratch (allocation-free rule: __device__ globals).
__device__ float g_xT[NN * BB];    // x transposed: [node][batch]
__device__ float g_accR[NN * BB];  // reaction messages, indexed by edge_i
__device__ float g_accD[NN * BB];  // diffusion messages, indexed by edge_j
__device__ float g_colR[NN];       // sum w_r over edge_j
__device__ float g_colD[NN];       // sum w_d over edge_i
__device__ float g_outT[NN * BB];  // output, node-major, pre-transpose

__device__ __forceinline__ void red_add_v4(float* addr, float4 v) {
    asm volatile("red.global.add.v4.f32 [%0], {%1,%2,%3,%4};"
                 :: "l"(addr), "f"(v.x), "f"(v.y), "f"(v.z), "f"(v.w)
                 : "memory");
}

// ---------------------------------------------------------------------------
// 1) Zero accumulators (kernel launch, graph-safe).
// ---------------------------------------------------------------------------
__global__ void zero_kernel() {
    int t = blockIdx.x * blockDim.x + threadIdx.x;
    const int total4 = (NN * BB) / 4;
    if (t < total4) {
        reinterpret_cast<float4*>(g_accR)[t] = make_float4(0.f, 0.f, 0.f, 0.f);
        reinterpret_cast<float4*>(g_accD)[t] = make_float4(0.f, 0.f, 0.f, 0.f);
    }
    if (t < NN) {
        g_colR[t] = 0.f;
        g_colD[t] = 0.f;
    }
}

// ---------------------------------------------------------------------------
// 2) Transpose input [BB, NN] -> g_xT [NN, BB]   (shared 32x33 tile)
// ---------------------------------------------------------------------------
__global__ void transpose_in_kernel(const float* __restrict__ src) {
    __shared__ float tile[32][33];
    int c = blockIdx.x * 32 + threadIdx.x;   // node index in src
    int rbase = blockIdx.y * 32;             // batch base
    #pragma unroll
    for (int k = threadIdx.y; k < 32; k += 8) {
        int r = rbase + k;
        if (r < BB && c < NN)
            tile[k][threadIdx.x] = src[(size_t)r * NN + c];
    }
    __syncthreads();
    int c2 = rbase + threadIdx.x;            // batch index in dst row
    int r2base = blockIdx.x * 32;            // node base in dst
    #pragma unroll
    for (int k = threadIdx.y; k < 32; k += 8) {
        int r2 = r2base + k;
        if (r2 < NN && c2 < BB)
            g_xT[(size_t)r2 * BB + c2] = tile[threadIdx.x][k];
    }
}

// ---------------------------------------------------------------------------
// 3) Edge kernel: 16 threads per edge, float4 (4 batches) per lane.
//    accR[i][:] += w_r[e] * xT[j][:]       (reaction msg,  seg by edge_i)
//    accD[j][:] += w_d[e] * xT[i][:]       (diffusion msg, seg by edge_j)
//    colR[j]    += w_r[e];  colD[i] += w_d[e]
// ---------------------------------------------------------------------------
__global__ void __launch_bounds__(256) edge_kernel(
    const int* __restrict__ ei, const int* __restrict__ ej,
    const float* __restrict__ wr, const float* __restrict__ wd, int E)
{
    int t = blockIdx.x * blockDim.x + threadIdx.x;
    int e = t >> 4;
    if (e >= E) return;
    int lane = t & 15;

    int   i   = __ldg(ei + e);
    int   j   = __ldg(ej + e);
    float wre = __ldg(wr + e);
    float wde = __ldg(wd + e);

    const float4* xj = reinterpret_cast<const float4*>(g_xT + (size_t)j * BB);
    const float4* xi = reinterpret_cast<const float4*>(g_xT + (size_t)i * BB);
    float4 vj = __ldg(xj + lane);
    float4 vi = __ldg(xi + lane);

    float4 r = make_float4(wre * vj.x, wre * vj.y, wre * vj.z, wre * vj.w);
    float4 d = make_float4(wde * vi.x, wde * vi.y, wde * vi.z, wde * vi.w);

    red_add_v4(g_accR + (size_t)i * BB + lane * 4, r);
    red_add_v4(g_accD + (size_t)j * BB + lane * 4, d);

    if (lane == 0) atomicAdd(g_colR + j, wre);
    if (lane == 1) atomicAdd(g_colD + i, wde);
}

// ---------------------------------------------------------------------------
// 4) Epilogue into node-major outT.
//    out[b,v] = tanh(colR[v]*x - msgR + br[v]) + (colD[v]*x - msgD + bd[v]) + x
// ---------------------------------------------------------------------------
__global__ void finalize_kernel(const float* __restrict__ br,
                                const float* __restrict__ bd)
{
    int t = blockIdx.x * blockDim.x + threadIdx.x;
    if (t >= NN * BB) return;
    int v = t >> 6;   // node index (BB = 64)
    float xv   = g_xT[t];
    float reac = g_colR[v] * xv - g_accR[t] + __ldg(br + v);
    float diff = g_colD[v] * xv - g_accD[t] + __ldg(bd + v);
    g_outT[t] = tanhf(reac) + diff + xv;
}

// ---------------------------------------------------------------------------
// 5) Transpose g_outT [NN, BB] -> out [BB, NN]
// ---------------------------------------------------------------------------
__global__ void transpose_out_kernel(float* __restrict__ dst) {
    __shared__ float tile[32][33];
    int c = blockIdx.x * 32 + threadIdx.x;   // batch index in src row
    int rbase = blockIdx.y * 32;             // node base
    #pragma unroll
    for (int k = threadIdx.y; k < 32; k += 8) {
        int r = rbase + k;
        if (r < NN && c < BB)
            tile[k][threadIdx.x] = g_outT[(size_t)r * BB + c];
    }
    __syncthreads();
    int c2 = rbase + threadIdx.x;            // node index in dst row
    int r2base = blockIdx.x * 32;            // batch base in dst
    #pragma unroll
    for (int k = threadIdx.y; k < 32; k += 8) {
        int r2 = r2base + k;
        if (r2 < BB && c2 < NN)
            dst[(size_t)r2 * NN + c2] = tile[threadIdx.x][k];
    }
}

// ---------------------------------------------------------------------------
// Launch
// Inputs (metadata order): 0:t[1] 1:input[B,N] 2:edge_i[E] 3:edge_j[E]
//                          4:weight_react[1,E] 5:weight_diff[1,E]
//                          6:bias_reaction[1,N] 7:bias_diffusion[1,N]
// Output: float32 [B, N]
// ---------------------------------------------------------------------------
extern "C" void kernel_launch(void* const* d_in, const int* in_sizes, int n_in,
                              void* d_out, int out_size)
{
    const float* input = (const float*)d_in[1];
    const int*   ei    = (const int*)  d_in[2];
    const int*   ej    = (const int*)  d_in[3];
    const float* wr    = (const float*)d_in[4];
    const float* wd    = (const float*)d_in[5];
    const float* br    = (const float*)d_in[6];
    const float* bd    = (const float*)d_in[7];
    float*       out   = (float*)d_out;
    const int E = in_sizes[2];

    // 1) zero accumulators
    {
        int threads = (NN * BB) / 4;  // covers colR/colD too (NN < threads)
        zero_kernel<<<(threads + 255) / 256, 256>>>();
    }

    // 2) transpose input -> xT
    {
        dim3 tb(32, 8);
        dim3 grid((NN + 31) / 32, (BB + 31) / 32);
        transpose_in_kernel<<<grid, tb>>>(input);
    }

    // 3) edge scatter (16 threads/edge)
    {
        long long threads = (long long)E * 16;
        int blocks = (int)((threads + 255) / 256);
        edge_kernel<<<blocks, 256>>>(ei, ej, wr, wd, E);
    }

    // 4) epilogue
    {
        int threads = NN * BB;
        finalize_kernel<<<(threads + 255) / 256, 256>>>(br, bd);
    }

    // 5) transpose outT -> out
    {
        dim3 tb(32, 8);
        dim3 grid((BB + 31) / 32, (NN + 31) / 32);
        transpose_out_kernel<<<grid, tb>>>(out);
    }
}

// round 16
// speedup vs baseline: 1.0052x; 1.0052x over previous
#include <cuda_runtime.h>

// Problem constants (fixed by the dataset).
#define NN 50000
#define BB 64
#define EE 1600000

// Scratch (allocation-free rule: __device__ globals).
__device__ float g_xT[NN * BB];    // x transposed: [node][batch]
__device__ float g_accR[NN * BB];  // reaction messages, indexed by edge_i
__device__ float g_accD[NN * BB];  // diffusion messages, indexed by edge_j
__device__ float g_colR[NN];       // sum w_r over edge_j
__device__ float g_colD[NN];       // sum w_d over edge_i
__device__ float g_outT[NN * BB];  // output, node-major, pre-transpose

__device__ __forceinline__ void red_add_v4(float* addr, float4 v) {
    asm volatile("red.global.add.v4.f32 [%0], {%1,%2,%3,%4};"
                 :: "l"(addr), "f"(v.x), "f"(v.y), "f"(v.z), "f"(v.w)
                 : "memory");
}

// ---------------------------------------------------------------------------
// 1) Zero accumulators (kernel launch, graph-safe).
// ---------------------------------------------------------------------------
__global__ void zero_kernel() {
    int t = blockIdx.x * blockDim.x + threadIdx.x;
    const int total4 = (NN * BB) / 4;
    if (t < total4) {
        reinterpret_cast<float4*>(g_accR)[t] = make_float4(0.f, 0.f, 0.f, 0.f);
        reinterpret_cast<float4*>(g_accD)[t] = make_float4(0.f, 0.f, 0.f, 0.f);
    }
    if (t < NN) {
        g_colR[t] = 0.f;
        g_colD[t] = 0.f;
    }
}

// ---------------------------------------------------------------------------
// 2) Transpose input [BB, NN] -> g_xT [NN, BB]   (shared 32x33 tile)
// ---------------------------------------------------------------------------
__global__ void transpose_in_kernel(const float* __restrict__ src) {
    __shared__ float tile[32][33];
    int c = blockIdx.x * 32 + threadIdx.x;   // node index in src
    int rbase = blockIdx.y * 32;             // batch base
    #pragma unroll
    for (int k = threadIdx.y; k < 32; k += 8) {
        int r = rbase + k;
        if (r < BB && c < NN)
            tile[k][threadIdx.x] = src[(size_t)r * NN + c];
    }
    __syncthreads();
    int c2 = rbase + threadIdx.x;            // batch index in dst row
    int r2base = blockIdx.x * 32;            // node base in dst
    #pragma unroll
    for (int k = threadIdx.y; k < 32; k += 8) {
        int r2 = r2base + k;
        if (r2 < NN && c2 < BB)
            g_xT[(size_t)r2 * BB + c2] = tile[threadIdx.x][k];
    }
}

// ---------------------------------------------------------------------------
// 3) Edge kernel: 16 threads per edge, float4 (4 batches) per lane.
//    accR[i][:] += w_r[e] * xT[j][:]       (reaction msg,  seg by edge_i)
//    accD[j][:] += w_d[e] * xT[i][:]       (diffusion msg, seg by edge_j)
//    colR[j]    += w_r[e];  colD[i] += w_d[e]
// ---------------------------------------------------------------------------
__global__ void __launch_bounds__(256) edge_kernel(
    const int* __restrict__ ei, const int* __restrict__ ej,
    const float* __restrict__ wr, const float* __restrict__ wd, int E)
{
    int t = blockIdx.x * blockDim.x + threadIdx.x;
    int e = t >> 4;
    if (e >= E) return;
    int lane = t & 15;

    int   i   = __ldg(ei + e);
    int   j   = __ldg(ej + e);
    float wre = __ldg(wr + e);
    float wde = __ldg(wd + e);

    const float4* xj = reinterpret_cast<const float4*>(g_xT + (size_t)j * BB);
    const float4* xi = reinterpret_cast<const float4*>(g_xT + (size_t)i * BB);
    float4 vj = __ldg(xj + lane);
    float4 vi = __ldg(xi + lane);

    float4 r = make_float4(wre * vj.x, wre * vj.y, wre * vj.z, wre * vj.w);
    float4 d = make_float4(wde * vi.x, wde * vi.y, wde * vi.z, wde * vi.w);

    red_add_v4(g_accR + (size_t)i * BB + lane * 4, r);
    red_add_v4(g_accD + (size_t)j * BB + lane * 4, d);

    if (lane == 0) atomicAdd(g_colR + j, wre);
    if (lane == 1) atomicAdd(g_colD + i, wde);
}

// ---------------------------------------------------------------------------
// 4) Epilogue into node-major outT.
//    out[b,v] = tanh(colR[v]*x - msgR + br[v]) + (colD[v]*x - msgD + bd[v]) + x
// ---------------------------------------------------------------------------
__global__ void finalize_kernel(const float* __restrict__ br,
                                const float* __restrict__ bd)
{
    int t = blockIdx.x * blockDim.x + threadIdx.x;
    if (t >= NN * BB) return;
    int v = t >> 6;   // node index (BB = 64)
    float xv   = g_xT[t];
    float reac = g_colR[v] * xv - g_accR[t] + __ldg(br + v);
    float diff = g_colD[v] * xv - g_accD[t] + __ldg(bd + v);
    g_outT[t] = tanhf(reac) + diff + xv;
}

// ---------------------------------------------------------------------------
// 5) Transpose g_outT [NN, BB] -> out [BB, NN]
// ---------------------------------------------------------------------------
__global__ void transpose_out_kernel(float* __restrict__ dst) {
    __shared__ float tile[32][33];
    int c = blockIdx.x * 32 + threadIdx.x;   // batch index in src row
    int rbase = blockIdx.y * 32;             // node base
    #pragma unroll
    for (int k = threadIdx.y; k < 32; k += 8) {
        int r = rbase + k;
        if (r < NN && c < BB)
            tile[k][threadIdx.x] = g_outT[(size_t)r * BB + c];
    }
    __syncthreads();
    int c2 = rbase + threadIdx.x;            // node index in dst row
    int r2base = blockIdx.x * 32;            // batch base in dst
    #pragma unroll
    for (int k = threadIdx.y; k < 32; k += 8) {
        int r2 = r2base + k;
        if (r2 < BB && c2 < NN)
            dst[(size_t)r2 * NN + c2] = tile[threadIdx.x][k];
    }
}

// ---------------------------------------------------------------------------
// Launch
// Inputs (metadata order): 0:t[1] 1:input[B,N] 2:edge_i[E] 3:edge_j[E]
//                          4:weight_react[1,E] 5:weight_diff[1,E]
//                          6:bias_reaction[1,N] 7:bias_diffusion[1,N]
// Output: float32 [B, N]
// ---------------------------------------------------------------------------
extern "C" void kernel_launch(void* const* d_in, const int* in_sizes, int n_in,
                              void* d_out, int out_size)
{
    const float* input = (const float*)d_in[1];
    const int*   ei    = (const int*)  d_in[2];
    const int*   ej    = (const int*)  d_in[3];
    const float* wr    = (const float*)d_in[4];
    const float* wd    = (const float*)d_in[5];
    const float* br    = (const float*)d_in[6];
    const float* bd    = (const float*)d_in[7];
    float*       out   = (float*)d_out;
    const int E = in_sizes[2];

    // 1) zero accumulators
    {
        int threads = (NN * BB) / 4;  // covers colR/colD too (NN < threads)
        zero_kernel<<<(threads + 255) / 256, 256>>>();
    }

    // 2) transpose input -> xT
    {
        dim3 tb(32, 8);
        dim3 grid((NN + 31) / 32, (BB + 31) / 32);
        transpose_in_kernel<<<grid, tb>>>(input);
    }

    // 3) edge scatter (16 threads/edge)
    {
        long long threads = (long long)E * 16;
        int blocks = (int)((threads + 255) / 256);
        edge_kernel<<<blocks, 256>>>(ei, ej, wr, wd, E);
    }

    // 4) epilogue
    {
        int threads = NN * BB;
        finalize_kernel<<<(threads + 255) / 256, 256>>>(br, bd);
    }

    // 5) transpose outT -> out
    {
        dim3 tb(32, 8);
        dim3 grid((BB + 31) / 32, (NN + 31) / 32);
        transpose_out_kernel<<<grid, tb>>>(out);
    }
}

// round 17
// speedup vs baseline: 1.0054x; 1.0002x over previous
#include <cuda_runtime.h>

// Problem constants (fixed by the dataset).
#define NN 50000
#define BB 64
#define EE 1600000

// Scratch (allocation-free rule: __device__ globals).
__device__ float g_xT[NN * BB];    // x transposed: [node][batch]
__device__ float g_accR[NN * BB];  // reaction messages, indexed by edge_i
__device__ float g_accD[NN * BB];  // diffusion messages, indexed by edge_j
__device__ float g_colR[NN];       // sum w_r over edge_j
__device__ float g_colD[NN];       // sum w_d over edge_i
__device__ float g_outT[NN * BB];  // output, node-major, pre-transpose

__device__ __forceinline__ void red_add_v4(float* addr, float4 v) {
    asm volatile("red.global.add.v4.f32 [%0], {%1,%2,%3,%4};"
                 :: "l"(addr), "f"(v.x), "f"(v.y), "f"(v.z), "f"(v.w)
                 : "memory");
}

// ---------------------------------------------------------------------------
// 1) Zero accumulators (kernel launch, graph-safe).
// ---------------------------------------------------------------------------
__global__ void zero_kernel() {
    int t = blockIdx.x * blockDim.x + threadIdx.x;
    const int total4 = (NN * BB) / 4;
    if (t < total4) {
        reinterpret_cast<float4*>(g_accR)[t] = make_float4(0.f, 0.f, 0.f, 0.f);
        reinterpret_cast<float4*>(g_accD)[t] = make_float4(0.f, 0.f, 0.f, 0.f);
    }
    if (t < NN) {
        g_colR[t] = 0.f;
        g_colD[t] = 0.f;
    }
}

// ---------------------------------------------------------------------------
// 2) Transpose input [BB, NN] -> g_xT [NN, BB]   (shared 32x33 tile)
// ---------------------------------------------------------------------------
__global__ void transpose_in_kernel(const float* __restrict__ src) {
    __shared__ float tile[32][33];
    int c = blockIdx.x * 32 + threadIdx.x;   // node index in src
    int rbase = blockIdx.y * 32;             // batch base
    #pragma unroll
    for (int k = threadIdx.y; k < 32; k += 8) {
        int r = rbase + k;
        if (r < BB && c < NN)
            tile[k][threadIdx.x] = src[(size_t)r * NN + c];
    }
    __syncthreads();
    int c2 = rbase + threadIdx.x;            // batch index in dst row
    int r2base = blockIdx.x * 32;            // node base in dst
    #pragma unroll
    for (int k = threadIdx.y; k < 32; k += 8) {
        int r2 = r2base + k;
        if (r2 < NN && c2 < BB)
            g_xT[(size_t)r2 * BB + c2] = tile[threadIdx.x][k];
    }
}

// ---------------------------------------------------------------------------
// 3) Edge kernel: 16 threads per edge, float4 (4 batches) per lane.
//    accR[i][:] += w_r[e] * xT[j][:]       (reaction msg,  seg by edge_i)
//    accD[j][:] += w_d[e] * xT[i][:]       (diffusion msg, seg by edge_j)
//    colR[j]    += w_r[e];  colD[i] += w_d[e]
// ---------------------------------------------------------------------------
__global__ void __launch_bounds__(256) edge_kernel(
    const int* __restrict__ ei, const int* __restrict__ ej,
    const float* __restrict__ wr, const float* __restrict__ wd, int E)
{
    int t = blockIdx.x * blockDim.x + threadIdx.x;
    int e = t >> 4;
    if (e >= E) return;
    int lane = t & 15;

    int   i   = __ldg(ei + e);
    int   j   = __ldg(ej + e);
    float wre = __ldg(wr + e);
    float wde = __ldg(wd + e);

    const float4* xj = reinterpret_cast<const float4*>(g_xT + (size_t)j * BB);
    const float4* xi = reinterpret_cast<const float4*>(g_xT + (size_t)i * BB);
    float4 vj = __ldg(xj + lane);
    float4 vi = __ldg(xi + lane);

    float4 r = make_float4(wre * vj.x, wre * vj.y, wre * vj.z, wre * vj.w);
    float4 d = make_float4(wde * vi.x, wde * vi.y, wde * vi.z, wde * vi.w);

    red_add_v4(g_accR + (size_t)i * BB + lane * 4, r);
    red_add_v4(g_accD + (size_t)j * BB + lane * 4, d);

    if (lane == 0) atomicAdd(g_colR + j, wre);
    if (lane == 1) atomicAdd(g_colD + i, wde);
}

// ---------------------------------------------------------------------------
// 4) Epilogue into node-major outT.
//    out[b,v] = tanh(colR[v]*x - msgR + br[v]) + (colD[v]*x - msgD + bd[v]) + x
// ---------------------------------------------------------------------------
__global__ void finalize_kernel(const float* __restrict__ br,
                                const float* __restrict__ bd)
{
    int t = blockIdx.x * blockDim.x + threadIdx.x;
    if (t >= NN * BB) return;
    int v = t >> 6;   // node index (BB = 64)
    float xv   = g_xT[t];
    float reac = g_colR[v] * xv - g_accR[t] + __ldg(br + v);
    float diff = g_colD[v] * xv - g_accD[t] + __ldg(bd + v);
    g_outT[t] = tanhf(reac) + diff + xv;
}

// ---------------------------------------------------------------------------
// 5) Transpose g_outT [NN, BB] -> out [BB, NN]
// ---------------------------------------------------------------------------
__global__ void transpose_out_kernel(float* __restrict__ dst) {
    __shared__ float tile[32][33];
    int c = blockIdx.x * 32 + threadIdx.x;   // batch index in src row
    int rbase = blockIdx.y * 32;             // node base
    #pragma unroll
    for (int k = threadIdx.y; k < 32; k += 8) {
        int r = rbase + k;
        if (r < NN && c < BB)
            tile[k][threadIdx.x] = g_outT[(size_t)r * BB + c];
    }
    __syncthreads();
    int c2 = rbase + threadIdx.x;            // node index in dst row
    int r2base = blockIdx.x * 32;            // batch base in dst
    #pragma unroll
    for (int k = threadIdx.y; k < 32; k += 8) {
        int r2 = r2base + k;
        if (r2 < BB && c2 < NN)
            dst[(size_t)r2 * NN + c2] = tile[threadIdx.x][k];
    }
}

// ---------------------------------------------------------------------------
// Launch
// Inputs (metadata order): 0:t[1] 1:input[B,N] 2:edge_i[E] 3:edge_j[E]
//                          4:weight_react[1,E] 5:weight_diff[1,E]
//                          6:bias_reaction[1,N] 7:bias_diffusion[1,N]
// Output: float32 [B, N]
// ---------------------------------------------------------------------------
extern "C" void kernel_launch(void* const* d_in, const int* in_sizes, int n_in,
                              void* d_out, int out_size)
{
    const float* input = (const float*)d_in[1];
    const int*   ei    = (const int*)  d_in[2];
    const int*   ej    = (const int*)  d_in[3];
    const float* wr    = (const float*)d_in[4];
    const float* wd    = (const float*)d_in[5];
    const float* br    = (const float*)d_in[6];
    const float* bd    = (const float*)d_in[7];
    float*       out   = (float*)d_out;
    const int E = in_sizes[2];

    // 1) zero accumulators
    {
        int threads = (NN * BB) / 4;  // covers colR/colD too (NN < threads)
        zero_kernel<<<(threads + 255) / 256, 256>>>();
    }

    // 2) transpose input -> xT
    {
        dim3 tb(32, 8);
        dim3 grid((NN + 31) / 32, (BB + 31) / 32);
        transpose_in_kernel<<<grid, tb>>>(input);
    }

    // 3) edge scatter (16 threads/edge)
    {
        long long threads = (long long)E * 16;
        int blocks = (int)((threads + 255) / 256);
        edge_kernel<<<blocks, 256>>>(ei, ej, wr, wd, E);
    }

    // 4) epilogue
    {
        int threads = NN * BB;
        finalize_kernel<<<(threads + 255) / 256, 256>>>(br, bd);
    }

    // 5) transpose outT -> out
    {
        dim3 tb(32, 8);
        dim3 grid((BB + 31) / 32, (NN + 31) / 32);
        transpose_out_kernel<<<grid, tb>>>(out);
    }
}